// round 11
// baseline (speedup 1.0000x reference)
#include <cuda_runtime.h>
#include <cuda_bf16.h>
#include <mma.h>
#include <cstdint>

using namespace nvcuda;

#define L_SEQ 3072
#define D_MODEL 512
#define N_TOKENS 3071

// ======================= scratch (allocation-free) =============================
__device__ float g_Q [L_SEQ * D_MODEL];
__device__ float g_K [L_SEQ * D_MODEL];
__device__ float g_V [L_SEQ * D_MODEL];
__device__ float g_A [L_SEQ * D_MODEL];
__device__ float g_XA[L_SEQ * D_MODEL];
__device__ float g_Y [L_SEQ * D_MODEL];
__device__ float g_X2[L_SEQ * D_MODEL];
__device__ int   g_SEG[L_SEQ];

// activation hi/lo pairs (two ping-pong pairs), 16B-aligned
__device__ uint4 g_AH1[L_SEQ * D_MODEL * 2 / 16];
__device__ uint4 g_AL1[L_SEQ * D_MODEL * 2 / 16];
__device__ uint4 g_AH2[L_SEQ * D_MODEL * 2 / 16];
__device__ uint4 g_AL2[L_SEQ * D_MODEL * 2 / 16];
__device__ uint4 g_WHI[6 * D_MODEL * D_MODEL * 2 / 16];
__device__ uint4 g_WLO[6 * D_MODEL * D_MODEL * 2 / 16];

// ======================= fused weight split (all 6 in one launch) =============
struct SplitSrc { const float* s[6]; };

__global__ void __launch_bounds__(256)
split6_kernel(SplitSrc S, __nv_bfloat16* __restrict__ hiBase,
              __nv_bfloat16* __restrict__ loBase, int n4)
{
    const int j = blockIdx.y;
    const float* src = S.s[j];
    __nv_bfloat16* hi = hiBase + j * (D_MODEL * D_MODEL);
    __nv_bfloat16* lo = loBase + j * (D_MODEL * D_MODEL);
    int i = blockIdx.x * blockDim.x + threadIdx.x;
    if (i >= n4) return;
    float4 v = ((const float4*)src)[i];
    __nv_bfloat16 h0 = __float2bfloat16(v.x);
    __nv_bfloat16 h1 = __float2bfloat16(v.y);
    __nv_bfloat16 h2 = __float2bfloat16(v.z);
    __nv_bfloat16 h3 = __float2bfloat16(v.w);
    __nv_bfloat16 l0 = __float2bfloat16(v.x - __bfloat162float(h0));
    __nv_bfloat16 l1 = __float2bfloat16(v.y - __bfloat162float(h1));
    __nv_bfloat16 l2 = __float2bfloat16(v.z - __bfloat162float(h2));
    __nv_bfloat16 l3 = __float2bfloat16(v.w - __bfloat162float(h3));
    __nv_bfloat162 hA(h0, h1), hB(h2, h3), lA(l0, l1), lB(l2, l3);
    uint2 uh, ul;
    uh.x = *(uint32_t*)&hA; uh.y = *(uint32_t*)&hB;
    ul.x = *(uint32_t*)&lA; ul.y = *(uint32_t*)&lB;
    ((uint2*)hi)[i] = uh;
    ((uint2*)lo)[i] = ul;
}

// ======================= WMMA bf16x3 pipelined GEMM ===========================
// C[M,N] = A[M,512] @ B[N,512]^T + bias ; A,B pre-split hi/lo bf16 K-major.
// CTA tile 128x64, K chunks of 32, cp.async double buffer.
// 128 threads = 4 warps; warp tile 32x64; B-fragments loaded JIT to cut regs;
// __launch_bounds__(128,3) -> 3 CTAs/SM (12 warps) for latency hiding.
struct GemmOut { const __nv_bfloat16* bh; const __nv_bfloat16* bl;
                 const float* bias; float* cF;
                 __nv_bfloat16* cHi; __nv_bfloat16* cLo; };
struct GemmOut3 { GemmOut m[3]; };

#define CH    32
#define NCHUNK (512 / CH)            // 16
#define LDSK  40                     // 32 + 8 pad
#define SM_AH 0
#define SM_AL (128 * LDSK)
#define SM_BH (2 * 128 * LDSK)
#define SM_BL (2 * 128 * LDSK + 64 * LDSK)
#define BUF_ELEMS (2 * 128 * LDSK + 2 * 64 * LDSK)   // 15360 bf16
#define GT_SMEM (2 * BUF_ELEMS * 2)                   // 61440 B

__device__ __forceinline__ uint32_t smem_u32(const void* p) {
    uint32_t a;
    asm("{ .reg .u64 t; cvta.to.shared.u64 t, %1; cvt.u32.u64 %0, t; }" : "=r"(a) : "l"(p));
    return a;
}
__device__ __forceinline__ void cp16(uint32_t sdst, const void* gsrc) {
    asm volatile("cp.async.cg.shared.global [%0], [%1], 16;" :: "r"(sdst), "l"(gsrc));
}

__global__ void __launch_bounds__(128, 3)
gemm_wmma(const __nv_bfloat16* __restrict__ Ahi, const __nv_bfloat16* __restrict__ Alo,
          GemmOut3 P, int act)
{
    extern __shared__ __align__(128) __nv_bfloat16 smem[];
    const GemmOut g = P.m[blockIdx.z];
    const uint32_t sb = smem_u32(smem);
    const int tid  = threadIdx.x;
    const int wid  = tid >> 5;     // 0..3 = M-warp
    const int lane = tid & 31;
    const int rowM0 = blockIdx.y * 128;
    const int colN0 = blockIdx.x * 64;

    const __nv_bfloat16* gAh = Ahi  + rowM0 * 512;
    const __nv_bfloat16* gAl = Alo  + rowM0 * 512;
    const __nv_bfloat16* gBh = g.bh + colN0 * 512;
    const __nv_bfloat16* gBl = g.bl + colN0 * 512;

    // per chunk (CH=32): A tile 128x32 = 512 16B-chunks -> 4/thread (hi,lo each);
    // B tile 64x32 = 256 chunks -> 2/thread (hi,lo each).
#define ISSUE(cc, buf) do {                                                          \
        const int koff = (cc) * CH;                                                  \
        const uint32_t bb = sb + (uint32_t)(buf) * (BUF_ELEMS * 2);                  \
        _Pragma("unroll")                                                            \
        for (int i = 0; i < 4; ++i) {                                                \
            int id = tid + i * 128;            /* 0..511 */                          \
            int r = id >> 2, c8 = (id & 3) * 8;                                      \
            cp16(bb + (SM_AH + r * LDSK + c8) * 2, gAh + r * 512 + koff + c8);       \
            cp16(bb + (SM_AL + r * LDSK + c8) * 2, gAl + r * 512 + koff + c8);       \
        }                                                                            \
        _Pragma("unroll")                                                            \
        for (int i = 0; i < 2; ++i) {                                                \
            int id = tid + i * 128;            /* 0..255 */                          \
            int r = id >> 2, c8 = (id & 3) * 8;                                      \
            cp16(bb + (SM_BH + r * LDSK + c8) * 2, gBh + r * 512 + koff + c8);       \
            cp16(bb + (SM_BL + r * LDSK + c8) * 2, gBl + r * 512 + koff + c8);       \
        }                                                                            \
        asm volatile("cp.async.commit_group;");                                      \
    } while (0)

    wmma::fragment<wmma::accumulator, 16, 16, 16, float> acc[2][4];
#pragma unroll
    for (int mt = 0; mt < 2; ++mt)
#pragma unroll
        for (int nt = 0; nt < 4; ++nt)
            wmma::fill_fragment(acc[mt][nt], 0.0f);

    ISSUE(0, 0);

    for (int c = 0; c < NCHUNK; ++c) {
        if (c < NCHUNK - 1) {
            ISSUE(c + 1, (c + 1) & 1);
            asm volatile("cp.async.wait_group 1;");
        } else {
            asm volatile("cp.async.wait_group 0;");
        }
        __syncthreads();

        const __nv_bfloat16* sAh = smem + (c & 1) * BUF_ELEMS + SM_AH;
        const __nv_bfloat16* sAl = smem + (c & 1) * BUF_ELEMS + SM_AL;
        const __nv_bfloat16* sBh = smem + (c & 1) * BUF_ELEMS + SM_BH;
        const __nv_bfloat16* sBl = smem + (c & 1) * BUF_ELEMS + SM_BL;

#pragma unroll
        for (int k16 = 0; k16 < CH / 16; ++k16) {
            wmma::fragment<wmma::matrix_a, 16, 16, 16, __nv_bfloat16, wmma::row_major> ah[2], al[2];
#pragma unroll
            for (int mt = 0; mt < 2; ++mt) {
                const int arow = wid * 32 + mt * 16;
                wmma::load_matrix_sync(ah[mt], sAh + arow * LDSK + k16 * 16, LDSK);
                wmma::load_matrix_sync(al[mt], sAl + arow * LDSK + k16 * 16, LDSK);
            }
#pragma unroll
            for (int nt = 0; nt < 4; ++nt) {
                wmma::fragment<wmma::matrix_b, 16, 16, 16, __nv_bfloat16, wmma::col_major> bh, bl;
                const int bcol = nt * 16;
                wmma::load_matrix_sync(bh, sBh + bcol * LDSK + k16 * 16, LDSK);
                wmma::load_matrix_sync(bl, sBl + bcol * LDSK + k16 * 16, LDSK);
#pragma unroll
                for (int mt = 0; mt < 2; ++mt) {
                    wmma::mma_sync(acc[mt][nt], ah[mt], bh, acc[mt][nt]);
                    wmma::mma_sync(acc[mt][nt], ah[mt], bl, acc[mt][nt]);
                    wmma::mma_sync(acc[mt][nt], al[mt], bh, acc[mt][nt]);
                }
            }
        }
        __syncthreads();
    }
#undef ISSUE

    // ---------------- epilogue: warp stages 32x64 f32 in smem -----------------
    float* warpArea = (float*)smem + wid * (32 * 64);
#pragma unroll
    for (int mt = 0; mt < 2; ++mt)
#pragma unroll
        for (int nt = 0; nt < 4; ++nt)
            wmma::store_matrix_sync(warpArea + mt * 16 * 64 + nt * 16,
                                    acc[mt][nt], 64, wmma::mem_row_major);
    __syncwarp();

    const int grow = rowM0 + wid * 32 + lane;
    const float* bi = g.bias + colN0;
    const float* srow = warpArea + lane * 64;
#pragma unroll
    for (int j = 0; j < 16; ++j) {
        float4 v  = *(const float4*)(srow + j * 4);
        float4 bz = *(const float4*)(bi + j * 4);
        float4 o;
        o.x = v.x + bz.x; o.y = v.y + bz.y; o.z = v.z + bz.z; o.w = v.w + bz.w;
        if (act) {
            o.x = o.x > 0.f ? o.x : 0.01f * o.x;
            o.y = o.y > 0.f ? o.y : 0.01f * o.y;
            o.z = o.z > 0.f ? o.z : 0.01f * o.z;
            o.w = o.w > 0.f ? o.w : 0.01f * o.w;
        }
        if (g.cF) *(float4*)(g.cF + grow * 512 + colN0 + j * 4) = o;
        if (g.cHi) {
            __nv_bfloat16 h0 = __float2bfloat16(o.x), h1 = __float2bfloat16(o.y);
            __nv_bfloat16 h2 = __float2bfloat16(o.z), h3 = __float2bfloat16(o.w);
            __nv_bfloat16 l0 = __float2bfloat16(o.x - __bfloat162float(h0));
            __nv_bfloat16 l1 = __float2bfloat16(o.y - __bfloat162float(h1));
            __nv_bfloat16 l2 = __float2bfloat16(o.z - __bfloat162float(h2));
            __nv_bfloat16 l3 = __float2bfloat16(o.w - __bfloat162float(h3));
            __nv_bfloat162 hA(h0, h1), hB(h2, h3), lA(l0, l1), lB(l2, l3);
            uint2 uh, ul;
            uh.x = *(uint32_t*)&hA; uh.y = *(uint32_t*)&hB;
            ul.x = *(uint32_t*)&lA; ul.y = *(uint32_t*)&lB;
            *(uint2*)(g.cHi + grow * 512 + colN0 + j * 4) = uh;
            *(uint2*)(g.cLo + grow * 512 + colN0 + j * 4) = ul;
        }
    }
}

// ======================= embedding (emits hi/lo directly) =====================
__global__ void embed_kernel(const int* __restrict__ idx,
                             const float* __restrict__ Wt, const float* __restrict__ bt,
                             const float* __restrict__ Wa, const float* __restrict__ ba,
                             const float* __restrict__ Wm, const float* __restrict__ bm,
                             const float* __restrict__ sos,
                             __nv_bfloat16* __restrict__ XH, __nv_bfloat16* __restrict__ XL)
{
    int n = blockIdx.x;
    int d = threadIdx.x;             // 512 threads
    float r;
    if (n == 0) {
        r = sos[d];
    } else {
        int id = idx[n - 1];
        int t  = id / 219;           // N_ARGS*N_MAPS = 73*3
        int a  = (id / 3) % 73;
        int m  = id % 3;
        r = bt[d] + ba[d] + bm[d];
        r += Wt[d * 15 + t];
        r += Wa[d * 73 + a];
        r += Wm[d * 3  + m];
    }
    __nv_bfloat16 h = __float2bfloat16(r);
    __nv_bfloat16 l = __float2bfloat16(r - __bfloat162float(h));
    XH[n * D_MODEL + d] = h;
    XL[n * D_MODEL + d] = l;
}

// ======================= segment-start parallel max-scan ======================
__global__ void __launch_bounds__(1024)
seg_kernel(const int* __restrict__ seq_masks, int* __restrict__ seg)
{
    __shared__ int bnd[L_SEQ];
    __shared__ int tmax[1024];
    const int t = threadIdx.x;
    int run = 0;
#pragma unroll
    for (int e = 0; e < 3; ++e) {
        int i = t * 3 + e;
        int v;
        if (i == 0)      v = 0;
        else if (i == 1) v = 1;
        else             v = (seq_masks[i - 1] == 0) ? i : 0;
        run = max(run, v);
        bnd[i] = run;
    }
    tmax[t] = run;
    __syncthreads();
    for (int o = 1; o < 1024; o <<= 1) {
        int u = (t >= o) ? tmax[t - o] : 0;
        __syncthreads();
        tmax[t] = max(tmax[t], u);
        __syncthreads();
    }
    int excl = (t == 0) ? 0 : tmax[t - 1];
#pragma unroll
    for (int e = 0; e < 3; ++e) {
        int i = t * 3 + e;
        seg[i] = max(bnd[i], excl);
    }
}

// ======================= segment-sparse attention (float4, emits hi/lo) =======
// 128 threads: warp w holds heads 2w, 2w+1; 16 lanes x float4 per head.
__global__ void __launch_bounds__(128)
attn_kernel(const float* __restrict__ Q, const float* __restrict__ K,
            const float* __restrict__ V, const int* __restrict__ seg,
            __nv_bfloat16* __restrict__ OH, __nv_bfloat16* __restrict__ OL)
{
    const int i    = blockIdx.x;
    const int w    = threadIdx.x >> 5;
    const int lane = threadIdx.x & 31;
    const int h    = (w << 1) + (lane >> 4);   // head 0..7
    const int sl   = lane & 15;
    const int base = (h << 6) + (sl << 2);     // h*64 + sl*4

    float4 q = *(const float4*)(Q + i * D_MODEL + base);
    q.x *= 0.125f; q.y *= 0.125f; q.z *= 0.125f; q.w *= 0.125f;

    float m = -1e30f, l = 0.f;
    float a0 = 0.f, a1 = 0.f, a2 = 0.f, a3 = 0.f;
    const int s = seg[i];

    int j = 0;
    bool first = true;
    for (;;) {
        float4 kv = *(const float4*)(K + j * D_MODEL + base);
        float p = q.x * kv.x + q.y * kv.y + q.z * kv.z + q.w * kv.w;
#pragma unroll
        for (int o = 8; o; o >>= 1) p += __shfl_xor_sync(0xffffffffu, p, o);
        float mnew = fmaxf(m, p);
        float corr = __expf(m - mnew);
        float pe   = __expf(p - mnew);
        float4 vv = *(const float4*)(V + j * D_MODEL + base);
        l  = l  * corr + pe;
        a0 = a0 * corr + pe * vv.x;
        a1 = a1 * corr + pe * vv.y;
        a2 = a2 * corr + pe * vv.z;
        a3 = a3 * corr + pe * vv.w;
        m = mnew;
        if (first) { first = false; j = s; } else { j++; }
        if (j >= i) break;
    }

    float inv = 1.f / l;
    float o0 = a0 * inv, o1 = a1 * inv, o2 = a2 * inv, o3 = a3 * inv;
    __nv_bfloat16 h0 = __float2bfloat16(o0), h1 = __float2bfloat16(o1);
    __nv_bfloat16 h2 = __float2bfloat16(o2), h3 = __float2bfloat16(o3);
    __nv_bfloat16 l0 = __float2bfloat16(o0 - __bfloat162float(h0));
    __nv_bfloat16 l1 = __float2bfloat16(o1 - __bfloat162float(h1));
    __nv_bfloat16 l2 = __float2bfloat16(o2 - __bfloat162float(h2));
    __nv_bfloat16 l3 = __float2bfloat16(o3 - __bfloat162float(h3));
    __nv_bfloat162 hA(h0, h1), hB(h2, h3), lA(l0, l1), lB(l2, l3);
    uint2 uh, ul;
    uh.x = *(uint32_t*)&hA; uh.y = *(uint32_t*)&hB;
    ul.x = *(uint32_t*)&lA; ul.y = *(uint32_t*)&lB;
    *(uint2*)(OH + i * D_MODEL + base) = uh;
    *(uint2*)(OL + i * D_MODEL + base) = ul;
}

// ======================= LayerNorm (residual opt; f32 + hi/lo outs) ==========
__global__ void __launch_bounds__(256)
ln_kernel(const float* __restrict__ X, const float* __restrict__ R,
          const float* __restrict__ g, const float* __restrict__ b,
          float* __restrict__ OutF,
          __nv_bfloat16* __restrict__ OutH, __nv_bfloat16* __restrict__ OutL)
{
    const int row = blockIdx.x;
    const int t   = threadIdx.x;
    float2 v = *(const float2*)(X + row * D_MODEL + (t << 1));
    if (R) {
        float2 r = *(const float2*)(R + row * D_MODEL + (t << 1));
        v.x += r.x; v.y += r.y;
    }
    float s  = v.x + v.y;
    float sq = v.x * v.x + v.y * v.y;
#pragma unroll
    for (int o = 16; o; o >>= 1) {
        s  += __shfl_xor_sync(0xffffffffu, s,  o);
        sq += __shfl_xor_sync(0xffffffffu, sq, o);
    }
    __shared__ float ss[8], sqs[8];
    const int warp = t >> 5, lane = t & 31;
    if (lane == 0) { ss[warp] = s; sqs[warp] = sq; }
    __syncthreads();
    if (warp == 0) {
        float a = (lane < 8) ? ss[lane]  : 0.f;
        float c = (lane < 8) ? sqs[lane] : 0.f;
#pragma unroll
        for (int o = 4; o; o >>= 1) {
            a += __shfl_xor_sync(0xffffffffu, a, o);
            c += __shfl_xor_sync(0xffffffffu, c, o);
        }
        if (lane == 0) { ss[0] = a; sqs[0] = c; }
    }
    __syncthreads();
    const float mu  = ss[0]  * (1.f / 512.f);
    const float var = sqs[0] * (1.f / 512.f) - mu * mu;
    const float inv = rsqrtf(var + 1e-5f);
    float2 gg = *(const float2*)(g + (t << 1));
    float2 bb = *(const float2*)(b + (t << 1));
    float ox = (v.x - mu) * inv * gg.x + bb.x;
    float oy = (v.y - mu) * inv * gg.y + bb.y;
    if (OutF) {
        float2 o; o.x = ox; o.y = oy;
        *(float2*)(OutF + row * D_MODEL + (t << 1)) = o;
    }
    if (OutH) {
        __nv_bfloat16 h0 = __float2bfloat16(ox), h1 = __float2bfloat16(oy);
        __nv_bfloat16 l0 = __float2bfloat16(ox - __bfloat162float(h0));
        __nv_bfloat16 l1 = __float2bfloat16(oy - __bfloat162float(h1));
        __nv_bfloat162 hv(h0, h1), lv(l0, l1);
        *(__nv_bfloat162*)(OutH + row * D_MODEL + (t << 1)) = hv;
        *(__nv_bfloat162*)(OutL + row * D_MODEL + (t << 1)) = lv;
    }
}

// ======================= host orchestration ===================================
#define W_ELEMS (D_MODEL * D_MODEL)
#define W_N4    (W_ELEMS / 4)

extern "C" void kernel_launch(void* const* d_in, const int* in_sizes, int n_in,
                              void* d_out, int out_size)
{
    const int*   idx  = (const int*)  d_in[0];
    const int*   seqm = (const int*)  d_in[1];
    const float* Wt   = (const float*)d_in[2];
    const float* bt   = (const float*)d_in[3];
    const float* Wa   = (const float*)d_in[4];
    const float* ba   = (const float*)d_in[5];
    const float* Wm   = (const float*)d_in[6];
    const float* bm   = (const float*)d_in[7];
    const float* sos  = (const float*)d_in[8];
    const float* Wq   = (const float*)d_in[9];
    const float* bq   = (const float*)d_in[10];
    const float* Wk   = (const float*)d_in[11];
    const float* bk   = (const float*)d_in[12];
    const float* Wv   = (const float*)d_in[13];
    const float* bv   = (const float*)d_in[14];
    const float* Wo   = (const float*)d_in[15];
    const float* bo   = (const float*)d_in[16];
    const float* W1   = (const float*)d_in[17];
    const float* b1   = (const float*)d_in[18];
    const float* W2   = (const float*)d_in[19];
    const float* b2   = (const float*)d_in[20];
    const float* g1   = (const float*)d_in[21];
    const float* be1  = (const float*)d_in[22];
    const float* g2   = (const float*)d_in[23];
    const float* be2  = (const float*)d_in[24];
    float* out = (float*)d_out;

    float *pQ, *pK, *pV, *pA, *pXA, *pY, *pX2;
    int* pSeg;
    __nv_bfloat16 *pAH1, *pAL1, *pAH2, *pAL2, *pWHI, *pWLO;
    cudaGetSymbolAddress((void**)&pQ,  g_Q);
    cudaGetSymbolAddress((void**)&pK,  g_K);
    cudaGetSymbolAddress((void**)&pV,  g_V);
    cudaGetSymbolAddress((void**)&pA,  g_A);
    cudaGetSymbolAddress((void**)&pXA, g_XA);
    cudaGetSymbolAddress((void**)&pY,  g_Y);
    cudaGetSymbolAddress((void**)&pX2, g_X2);
    cudaGetSymbolAddress((void**)&pSeg, g_SEG);
    cudaGetSymbolAddress((void**)&pAH1, g_AH1);
    cudaGetSymbolAddress((void**)&pAL1, g_AL1);
    cudaGetSymbolAddress((void**)&pAH2, g_AH2);
    cudaGetSymbolAddress((void**)&pAL2, g_AL2);
    cudaGetSymbolAddress((void**)&pWHI, g_WHI);
    cudaGetSymbolAddress((void**)&pWLO, g_WLO);

    cudaFuncSetAttribute(gemm_wmma, cudaFuncAttributeMaxDynamicSharedMemorySize, GT_SMEM);

    // weight splits: order q,k,v,o,w1,w2 — single fused launch
    {
        SplitSrc S; S.s[0] = Wq; S.s[1] = Wk; S.s[2] = Wv;
        S.s[3] = Wo; S.s[4] = W1; S.s[5] = W2;
        dim3 sg(W_N4 / 256, 6);
        split6_kernel<<<sg, 256>>>(S, pWHI, pWLO, W_N4);
    }

    embed_kernel<<<L_SEQ, D_MODEL>>>(idx, Wt, bt, Wa, ba, Wm, bm, sos, pAH1, pAL1);
    seg_kernel<<<1, 1024>>>(seqm, pSeg);

    const __nv_bfloat16* wh[6]; const __nv_bfloat16* wl[6];
    for (int j = 0; j < 6; ++j) { wh[j] = pWHI + j * W_ELEMS; wl[j] = pWLO + j * W_ELEMS; }

    dim3 grid1(8, 24, 1), grid3(8, 24, 3);

    for (int layer = 0; layer < 2; ++layer) {
        // QKV: pair1 -> f32 Q,K,V
        {
            GemmOut3 P;
            P.m[0] = {wh[0], wl[0], bq, pQ, nullptr, nullptr};
            P.m[1] = {wh[1], wl[1], bk, pK, nullptr, nullptr};
            P.m[2] = {wh[2], wl[2], bv, pV, nullptr, nullptr};
            gemm_wmma<<<grid3, 128, GT_SMEM>>>(pAH1, pAL1, P, 0);
        }
        // attention -> pair2 hi/lo
        attn_kernel<<<L_SEQ, 128>>>(pQ, pK, pV, pSeg, pAH2, pAL2);
        // Wo: pair2 -> f32 A
        {
            GemmOut3 P; P.m[0] = {wh[3], wl[3], bo, pA, nullptr, nullptr};
            P.m[1] = P.m[0]; P.m[2] = P.m[0];
            gemm_wmma<<<grid1, 128, GT_SMEM>>>(pAH2, pAL2, P, 0);
        }
        // ln1: A -> f32 XA + pair1 hi/lo
        ln_kernel<<<L_SEQ, 256>>>(pA, nullptr, g1, be1, pXA, pAH1, pAL1);
        // FF1 (leaky): pair1 -> pair2 hi/lo (no f32)
        {
            GemmOut3 P; P.m[0] = {wh[4], wl[4], b1, nullptr, pAH2, pAL2};
            P.m[1] = P.m[0]; P.m[2] = P.m[0];
            gemm_wmma<<<grid1, 128, GT_SMEM>>>(pAH1, pAL1, P, 1);
        }
        // FF2: pair2 -> f32 Y
        {
            GemmOut3 P; P.m[0] = {wh[5], wl[5], b2, pY, nullptr, nullptr};
            P.m[1] = P.m[0]; P.m[2] = P.m[0];
            gemm_wmma<<<grid1, 128, GT_SMEM>>>(pAH2, pAL2, P, 0);
        }
        // ln2: Y + XA -> f32 (x2 or out) + pair1 hi/lo for next layer QKV
        ln_kernel<<<L_SEQ, 256>>>(pY, pXA, g2, be2,
                                  (layer == 0) ? pX2 : out, pAH1, pAL1);
    }
}

// round 12
// speedup vs baseline: 1.0730x; 1.0730x over previous
#include <cuda_runtime.h>
#include <cuda_bf16.h>
#include <mma.h>
#include <cstdint>

using namespace nvcuda;

#define L_SEQ 3072
#define D_MODEL 512
#define N_TOKENS 3071

// ======================= scratch (allocation-free) =============================
__device__ float g_Q [L_SEQ * D_MODEL];
__device__ float g_K [L_SEQ * D_MODEL];
__device__ float g_V [L_SEQ * D_MODEL];
__device__ float g_A [L_SEQ * D_MODEL];
__device__ float g_XA[L_SEQ * D_MODEL];
__device__ float g_Y [L_SEQ * D_MODEL];
__device__ float g_X2[L_SEQ * D_MODEL];
__device__ int   g_SEG[L_SEQ];

// activation hi/lo pairs (two ping-pong pairs), 16B-aligned
__device__ uint4 g_AH1[L_SEQ * D_MODEL * 2 / 16];
__device__ uint4 g_AL1[L_SEQ * D_MODEL * 2 / 16];
__device__ uint4 g_AH2[L_SEQ * D_MODEL * 2 / 16];
__device__ uint4 g_AL2[L_SEQ * D_MODEL * 2 / 16];
__device__ uint4 g_WHI[6 * D_MODEL * D_MODEL * 2 / 16];
__device__ uint4 g_WLO[6 * D_MODEL * D_MODEL * 2 / 16];

// ======================= fused weight split (all 6 in one launch) =============
struct SplitSrc { const float* s[6]; };

__global__ void __launch_bounds__(256)
split6_kernel(SplitSrc S, __nv_bfloat16* __restrict__ hiBase,
              __nv_bfloat16* __restrict__ loBase, int n4)
{
    const int j = blockIdx.y;
    const float* src = S.s[j];
    __nv_bfloat16* hi = hiBase + j * (D_MODEL * D_MODEL);
    __nv_bfloat16* lo = loBase + j * (D_MODEL * D_MODEL);
    int i = blockIdx.x * blockDim.x + threadIdx.x;
    if (i >= n4) return;
    float4 v = ((const float4*)src)[i];
    __nv_bfloat16 h0 = __float2bfloat16(v.x);
    __nv_bfloat16 h1 = __float2bfloat16(v.y);
    __nv_bfloat16 h2 = __float2bfloat16(v.z);
    __nv_bfloat16 h3 = __float2bfloat16(v.w);
    __nv_bfloat16 l0 = __float2bfloat16(v.x - __bfloat162float(h0));
    __nv_bfloat16 l1 = __float2bfloat16(v.y - __bfloat162float(h1));
    __nv_bfloat16 l2 = __float2bfloat16(v.z - __bfloat162float(h2));
    __nv_bfloat16 l3 = __float2bfloat16(v.w - __bfloat162float(h3));
    __nv_bfloat162 hA(h0, h1), hB(h2, h3), lA(l0, l1), lB(l2, l3);
    uint2 uh, ul;
    uh.x = *(uint32_t*)&hA; uh.y = *(uint32_t*)&hB;
    ul.x = *(uint32_t*)&lA; ul.y = *(uint32_t*)&lB;
    ((uint2*)hi)[i] = uh;
    ((uint2*)lo)[i] = ul;
}

// ======================= WMMA bf16x3 pipelined GEMM ===========================
// C[M,N] = A[M,512] @ B[N,512]^T + bias ; A,B pre-split hi/lo bf16 K-major.
// CTA tile 128x64, K chunks of 64, cp.async double buffer.
// 128 threads = 4 warps; warp tile 32x64 (2x4 fragments).
// MMA passes ordered pass-major (hh, hl, lh) so 8 independent MMAs sit between
// consecutive writes to the same accumulator (ILP for the tensor pipe).
struct GemmOut { const __nv_bfloat16* bh; const __nv_bfloat16* bl;
                 const float* bias; float* cF;
                 __nv_bfloat16* cHi; __nv_bfloat16* cLo; };
struct GemmOut3 { GemmOut m[3]; };

#define CH    64
#define NCHUNK (512 / CH)            // 8
#define LDSK  72
#define SM_AH 0
#define SM_AL (128 * LDSK)
#define SM_BH (2 * 128 * LDSK)
#define SM_BL (2 * 128 * LDSK + 64 * LDSK)
#define BUF_ELEMS (2 * 128 * LDSK + 2 * 64 * LDSK)   // 27648 bf16
#define GT_SMEM (2 * BUF_ELEMS * 2)                   // 110592 B

__device__ __forceinline__ uint32_t smem_u32(const void* p) {
    uint32_t a;
    asm("{ .reg .u64 t; cvta.to.shared.u64 t, %1; cvt.u32.u64 %0, t; }" : "=r"(a) : "l"(p));
    return a;
}
__device__ __forceinline__ void cp16(uint32_t sdst, const void* gsrc) {
    asm volatile("cp.async.cg.shared.global [%0], [%1], 16;" :: "r"(sdst), "l"(gsrc));
}

__global__ void __launch_bounds__(128, 2)
gemm_wmma(const __nv_bfloat16* __restrict__ Ahi, const __nv_bfloat16* __restrict__ Alo,
          GemmOut3 P, int act)
{
    extern __shared__ __align__(128) __nv_bfloat16 smem[];
    const GemmOut g = P.m[blockIdx.z];
    const uint32_t sb = smem_u32(smem);
    const int tid  = threadIdx.x;
    const int wid  = tid >> 5;     // 0..3 = M-warp
    const int lane = tid & 31;
    const int rowM0 = blockIdx.y * 128;
    const int colN0 = blockIdx.x * 64;

    const __nv_bfloat16* gAh = Ahi  + rowM0 * 512;
    const __nv_bfloat16* gAl = Alo  + rowM0 * 512;
    const __nv_bfloat16* gBh = g.bh + colN0 * 512;
    const __nv_bfloat16* gBl = g.bl + colN0 * 512;

#define ISSUE(cc, buf) do {                                                          \
        const int koff = (cc) * CH;                                                  \
        const uint32_t bb = sb + (uint32_t)(buf) * (BUF_ELEMS * 2);                  \
        _Pragma("unroll")                                                            \
        for (int i = 0; i < 8; ++i) {                                                \
            int id = tid + i * 128;            /* 0..1023 */                         \
            int r = id >> 3, c8 = (id & 7) * 8;                                      \
            cp16(bb + (SM_AH + r * LDSK + c8) * 2, gAh + r * 512 + koff + c8);       \
            cp16(bb + (SM_AL + r * LDSK + c8) * 2, gAl + r * 512 + koff + c8);       \
        }                                                                            \
        _Pragma("unroll")                                                            \
        for (int i = 0; i < 4; ++i) {                                                \
            int id = tid + i * 128;            /* 0..511 */                          \
            int r = id >> 3, c8 = (id & 7) * 8;                                      \
            cp16(bb + (SM_BH + r * LDSK + c8) * 2, gBh + r * 512 + koff + c8);       \
            cp16(bb + (SM_BL + r * LDSK + c8) * 2, gBl + r * 512 + koff + c8);       \
        }                                                                            \
        asm volatile("cp.async.commit_group;");                                      \
    } while (0)

    wmma::fragment<wmma::accumulator, 16, 16, 16, float> acc[2][4];
#pragma unroll
    for (int mt = 0; mt < 2; ++mt)
#pragma unroll
        for (int nt = 0; nt < 4; ++nt)
            wmma::fill_fragment(acc[mt][nt], 0.0f);

    ISSUE(0, 0);

    for (int c = 0; c < NCHUNK; ++c) {
        if (c < NCHUNK - 1) {
            ISSUE(c + 1, (c + 1) & 1);
            asm volatile("cp.async.wait_group 1;");
        } else {
            asm volatile("cp.async.wait_group 0;");
        }
        __syncthreads();

        const __nv_bfloat16* sAh = smem + (c & 1) * BUF_ELEMS + SM_AH;
        const __nv_bfloat16* sAl = smem + (c & 1) * BUF_ELEMS + SM_AL;
        const __nv_bfloat16* sBh = smem + (c & 1) * BUF_ELEMS + SM_BH;
        const __nv_bfloat16* sBl = smem + (c & 1) * BUF_ELEMS + SM_BL;

#pragma unroll
        for (int k16 = 0; k16 < CH / 16; ++k16) {
            wmma::fragment<wmma::matrix_a, 16, 16, 16, __nv_bfloat16, wmma::row_major> ah[2], al[2];
            wmma::fragment<wmma::matrix_b, 16, 16, 16, __nv_bfloat16, wmma::col_major> bh[4], bl[4];
#pragma unroll
            for (int mt = 0; mt < 2; ++mt) {
                const int arow = wid * 32 + mt * 16;
                wmma::load_matrix_sync(ah[mt], sAh + arow * LDSK + k16 * 16, LDSK);
                wmma::load_matrix_sync(al[mt], sAl + arow * LDSK + k16 * 16, LDSK);
            }
#pragma unroll
            for (int nt = 0; nt < 4; ++nt) {
                const int bcol = nt * 16;
                wmma::load_matrix_sync(bh[nt], sBh + bcol * LDSK + k16 * 16, LDSK);
                wmma::load_matrix_sync(bl[nt], sBl + bcol * LDSK + k16 * 16, LDSK);
            }
            // pass-major: 8 independent MMAs between touches of the same acc
#pragma unroll
            for (int mt = 0; mt < 2; ++mt)
#pragma unroll
                for (int nt = 0; nt < 4; ++nt)
                    wmma::mma_sync(acc[mt][nt], ah[mt], bh[nt], acc[mt][nt]);
#pragma unroll
            for (int mt = 0; mt < 2; ++mt)
#pragma unroll
                for (int nt = 0; nt < 4; ++nt)
                    wmma::mma_sync(acc[mt][nt], ah[mt], bl[nt], acc[mt][nt]);
#pragma unroll
            for (int mt = 0; mt < 2; ++mt)
#pragma unroll
                for (int nt = 0; nt < 4; ++nt)
                    wmma::mma_sync(acc[mt][nt], al[mt], bh[nt], acc[mt][nt]);
        }
        __syncthreads();
    }
#undef ISSUE

    // ---------------- epilogue: warp stages 32x64 f32 in smem -----------------
    float* warpArea = (float*)smem + wid * (32 * 64);
#pragma unroll
    for (int mt = 0; mt < 2; ++mt)
#pragma unroll
        for (int nt = 0; nt < 4; ++nt)
            wmma::store_matrix_sync(warpArea + mt * 16 * 64 + nt * 16,
                                    acc[mt][nt], 64, wmma::mem_row_major);
    __syncwarp();

    const int grow = rowM0 + wid * 32 + lane;
    const float* bi = g.bias + colN0;
    const float* srow = warpArea + lane * 64;
#pragma unroll
    for (int j = 0; j < 16; ++j) {
        float4 v  = *(const float4*)(srow + j * 4);
        float4 bz = *(const float4*)(bi + j * 4);
        float4 o;
        o.x = v.x + bz.x; o.y = v.y + bz.y; o.z = v.z + bz.z; o.w = v.w + bz.w;
        if (act) {
            o.x = o.x > 0.f ? o.x : 0.01f * o.x;
            o.y = o.y > 0.f ? o.y : 0.01f * o.y;
            o.z = o.z > 0.f ? o.z : 0.01f * o.z;
            o.w = o.w > 0.f ? o.w : 0.01f * o.w;
        }
        if (g.cF) *(float4*)(g.cF + grow * 512 + colN0 + j * 4) = o;
        if (g.cHi) {
            __nv_bfloat16 h0 = __float2bfloat16(o.x), h1 = __float2bfloat16(o.y);
            __nv_bfloat16 h2 = __float2bfloat16(o.z), h3 = __float2bfloat16(o.w);
            __nv_bfloat16 l0 = __float2bfloat16(o.x - __bfloat162float(h0));
            __nv_bfloat16 l1 = __float2bfloat16(o.y - __bfloat162float(h1));
            __nv_bfloat16 l2 = __float2bfloat16(o.z - __bfloat162float(h2));
            __nv_bfloat16 l3 = __float2bfloat16(o.w - __bfloat162float(h3));
            __nv_bfloat162 hA(h0, h1), hB(h2, h3), lA(l0, l1), lB(l2, l3);
            uint2 uh, ul;
            uh.x = *(uint32_t*)&hA; uh.y = *(uint32_t*)&hB;
            ul.x = *(uint32_t*)&lA; ul.y = *(uint32_t*)&lB;
            *(uint2*)(g.cHi + grow * 512 + colN0 + j * 4) = uh;
            *(uint2*)(g.cLo + grow * 512 + colN0 + j * 4) = ul;
        }
    }
}

// ======================= embedding (emits hi/lo directly) =====================
__global__ void embed_kernel(const int* __restrict__ idx,
                             const float* __restrict__ Wt, const float* __restrict__ bt,
                             const float* __restrict__ Wa, const float* __restrict__ ba,
                             const float* __restrict__ Wm, const float* __restrict__ bm,
                             const float* __restrict__ sos,
                             __nv_bfloat16* __restrict__ XH, __nv_bfloat16* __restrict__ XL)
{
    int n = blockIdx.x;
    int d = threadIdx.x;             // 512 threads
    float r;
    if (n == 0) {
        r = sos[d];
    } else {
        int id = idx[n - 1];
        int t  = id / 219;           // N_ARGS*N_MAPS = 73*3
        int a  = (id / 3) % 73;
        int m  = id % 3;
        r = bt[d] + ba[d] + bm[d];
        r += Wt[d * 15 + t];
        r += Wa[d * 73 + a];
        r += Wm[d * 3  + m];
    }
    __nv_bfloat16 h = __float2bfloat16(r);
    __nv_bfloat16 l = __float2bfloat16(r - __bfloat162float(h));
    XH[n * D_MODEL + d] = h;
    XL[n * D_MODEL + d] = l;
}

// ======================= segment-start parallel max-scan ======================
__global__ void __launch_bounds__(1024)
seg_kernel(const int* __restrict__ seq_masks, int* __restrict__ seg)
{
    __shared__ int bnd[L_SEQ];
    __shared__ int tmax[1024];
    const int t = threadIdx.x;
    int run = 0;
#pragma unroll
    for (int e = 0; e < 3; ++e) {
        int i = t * 3 + e;
        int v;
        if (i == 0)      v = 0;
        else if (i == 1) v = 1;
        else             v = (seq_masks[i - 1] == 0) ? i : 0;
        run = max(run, v);
        bnd[i] = run;
    }
    tmax[t] = run;
    __syncthreads();
    for (int o = 1; o < 1024; o <<= 1) {
        int u = (t >= o) ? tmax[t - o] : 0;
        __syncthreads();
        tmax[t] = max(tmax[t], u);
        __syncthreads();
    }
    int excl = (t == 0) ? 0 : tmax[t - 1];
#pragma unroll
    for (int e = 0; e < 3; ++e) {
        int i = t * 3 + e;
        seg[i] = max(bnd[i], excl);
    }
}

// ======================= segment-sparse attention (float4, emits hi/lo) =======
// 128 threads: warp w holds heads 2w, 2w+1; 16 lanes x float4 per head.
__global__ void __launch_bounds__(128)
attn_kernel(const float* __restrict__ Q, const float* __restrict__ K,
            const float* __restrict__ V, const int* __restrict__ seg,
            __nv_bfloat16* __restrict__ OH, __nv_bfloat16* __restrict__ OL)
{
    const int i    = blockIdx.x;
    const int w    = threadIdx.x >> 5;
    const int lane = threadIdx.x & 31;
    const int h    = (w << 1) + (lane >> 4);   // head 0..7
    const int sl   = lane & 15;
    const int base = (h << 6) + (sl << 2);     // h*64 + sl*4

    float4 q = *(const float4*)(Q + i * D_MODEL + base);
    q.x *= 0.125f; q.y *= 0.125f; q.z *= 0.125f; q.w *= 0.125f;

    float m = -1e30f, l = 0.f;
    float a0 = 0.f, a1 = 0.f, a2 = 0.f, a3 = 0.f;
    const int s = seg[i];

    int j = 0;
    bool first = true;
    for (;;) {
        float4 kv = *(const float4*)(K + j * D_MODEL + base);
        float p = q.x * kv.x + q.y * kv.y + q.z * kv.z + q.w * kv.w;
#pragma unroll
        for (int o = 8; o; o >>= 1) p += __shfl_xor_sync(0xffffffffu, p, o);
        float mnew = fmaxf(m, p);
        float corr = __expf(m - mnew);
        float pe   = __expf(p - mnew);
        float4 vv = *(const float4*)(V + j * D_MODEL + base);
        l  = l  * corr + pe;
        a0 = a0 * corr + pe * vv.x;
        a1 = a1 * corr + pe * vv.y;
        a2 = a2 * corr + pe * vv.z;
        a3 = a3 * corr + pe * vv.w;
        m = mnew;
        if (first) { first = false; j = s; } else { j++; }
        if (j >= i) break;
    }

    float inv = 1.f / l;
    float o0 = a0 * inv, o1 = a1 * inv, o2 = a2 * inv, o3 = a3 * inv;
    __nv_bfloat16 h0 = __float2bfloat16(o0), h1 = __float2bfloat16(o1);
    __nv_bfloat16 h2 = __float2bfloat16(o2), h3 = __float2bfloat16(o3);
    __nv_bfloat16 l0 = __float2bfloat16(o0 - __bfloat162float(h0));
    __nv_bfloat16 l1 = __float2bfloat16(o1 - __bfloat162float(h1));
    __nv_bfloat16 l2 = __float2bfloat16(o2 - __bfloat162float(h2));
    __nv_bfloat16 l3 = __float2bfloat16(o3 - __bfloat162float(h3));
    __nv_bfloat162 hA(h0, h1), hB(h2, h3), lA(l0, l1), lB(l2, l3);
    uint2 uh, ul;
    uh.x = *(uint32_t*)&hA; uh.y = *(uint32_t*)&hB;
    ul.x = *(uint32_t*)&lA; ul.y = *(uint32_t*)&lB;
    *(uint2*)(OH + i * D_MODEL + base) = uh;
    *(uint2*)(OL + i * D_MODEL + base) = ul;
}

// ======================= LayerNorm (residual opt; f32 + hi/lo outs) ==========
__global__ void __launch_bounds__(256)
ln_kernel(const float* __restrict__ X, const float* __restrict__ R,
          const float* __restrict__ g, const float* __restrict__ b,
          float* __restrict__ OutF,
          __nv_bfloat16* __restrict__ OutH, __nv_bfloat16* __restrict__ OutL)
{
    const int row = blockIdx.x;
    const int t   = threadIdx.x;
    float2 v = *(const float2*)(X + row * D_MODEL + (t << 1));
    if (R) {
        float2 r = *(const float2*)(R + row * D_MODEL + (t << 1));
        v.x += r.x; v.y += r.y;
    }
    float s  = v.x + v.y;
    float sq = v.x * v.x + v.y * v.y;
#pragma unroll
    for (int o = 16; o; o >>= 1) {
        s  += __shfl_xor_sync(0xffffffffu, s,  o);
        sq += __shfl_xor_sync(0xffffffffu, sq, o);
    }
    __shared__ float ss[8], sqs[8];
    const int warp = t >> 5, lane = t & 31;
    if (lane == 0) { ss[warp] = s; sqs[warp] = sq; }
    __syncthreads();
    if (warp == 0) {
        float a = (lane < 8) ? ss[lane]  : 0.f;
        float c = (lane < 8) ? sqs[lane] : 0.f;
#pragma unroll
        for (int o = 4; o; o >>= 1) {
            a += __shfl_xor_sync(0xffffffffu, a, o);
            c += __shfl_xor_sync(0xffffffffu, c, o);
        }
        if (lane == 0) { ss[0] = a; sqs[0] = c; }
    }
    __syncthreads();
    const float mu  = ss[0]  * (1.f / 512.f);
    const float var = sqs[0] * (1.f / 512.f) - mu * mu;
    const float inv = rsqrtf(var + 1e-5f);
    float2 gg = *(const float2*)(g + (t << 1));
    float2 bb = *(const float2*)(b + (t << 1));
    float ox = (v.x - mu) * inv * gg.x + bb.x;
    float oy = (v.y - mu) * inv * gg.y + bb.y;
    if (OutF) {
        float2 o; o.x = ox; o.y = oy;
        *(float2*)(OutF + row * D_MODEL + (t << 1)) = o;
    }
    if (OutH) {
        __nv_bfloat16 h0 = __float2bfloat16(ox), h1 = __float2bfloat16(oy);
        __nv_bfloat16 l0 = __float2bfloat16(ox - __bfloat162float(h0));
        __nv_bfloat16 l1 = __float2bfloat16(oy - __bfloat162float(h1));
        __nv_bfloat162 hv(h0, h1), lv(l0, l1);
        *(__nv_bfloat162*)(OutH + row * D_MODEL + (t << 1)) = hv;
        *(__nv_bfloat162*)(OutL + row * D_MODEL + (t << 1)) = lv;
    }
}

// ======================= host orchestration ===================================
#define W_ELEMS (D_MODEL * D_MODEL)
#define W_N4    (W_ELEMS / 4)

extern "C" void kernel_launch(void* const* d_in, const int* in_sizes, int n_in,
                              void* d_out, int out_size)
{
    const int*   idx  = (const int*)  d_in[0];
    const int*   seqm = (const int*)  d_in[1];
    const float* Wt   = (const float*)d_in[2];
    const float* bt   = (const float*)d_in[3];
    const float* Wa   = (const float*)d_in[4];
    const float* ba   = (const float*)d_in[5];
    const float* Wm   = (const float*)d_in[6];
    const float* bm   = (const float*)d_in[7];
    const float* sos  = (const float*)d_in[8];
    const float* Wq   = (const float*)d_in[9];
    const float* bq   = (const float*)d_in[10];
    const float* Wk   = (const float*)d_in[11];
    const float* bk   = (const float*)d_in[12];
    const float* Wv   = (const float*)d_in[13];
    const float* bv   = (const float*)d_in[14];
    const float* Wo   = (const float*)d_in[15];
    const float* bo   = (const float*)d_in[16];
    const float* W1   = (const float*)d_in[17];
    const float* b1   = (const float*)d_in[18];
    const float* W2   = (const float*)d_in[19];
    const float* b2   = (const float*)d_in[20];
    const float* g1   = (const float*)d_in[21];
    const float* be1  = (const float*)d_in[22];
    const float* g2   = (const float*)d_in[23];
    const float* be2  = (const float*)d_in[24];
    float* out = (float*)d_out;

    float *pQ, *pK, *pV, *pA, *pXA, *pY, *pX2;
    int* pSeg;
    __nv_bfloat16 *pAH1, *pAL1, *pAH2, *pAL2, *pWHI, *pWLO;
    cudaGetSymbolAddress((void**)&pQ,  g_Q);
    cudaGetSymbolAddress((void**)&pK,  g_K);
    cudaGetSymbolAddress((void**)&pV,  g_V);
    cudaGetSymbolAddress((void**)&pA,  g_A);
    cudaGetSymbolAddress((void**)&pXA, g_XA);
    cudaGetSymbolAddress((void**)&pY,  g_Y);
    cudaGetSymbolAddress((void**)&pX2, g_X2);
    cudaGetSymbolAddress((void**)&pSeg, g_SEG);
    cudaGetSymbolAddress((void**)&pAH1, g_AH1);
    cudaGetSymbolAddress((void**)&pAL1, g_AL1);
    cudaGetSymbolAddress((void**)&pAH2, g_AH2);
    cudaGetSymbolAddress((void**)&pAL2, g_AL2);
    cudaGetSymbolAddress((void**)&pWHI, g_WHI);
    cudaGetSymbolAddress((void**)&pWLO, g_WLO);

    cudaFuncSetAttribute(gemm_wmma, cudaFuncAttributeMaxDynamicSharedMemorySize, GT_SMEM);

    // weight splits: order q,k,v,o,w1,w2 — single fused launch
    {
        SplitSrc S; S.s[0] = Wq; S.s[1] = Wk; S.s[2] = Wv;
        S.s[3] = Wo; S.s[4] = W1; S.s[5] = W2;
        dim3 sg(W_N4 / 256, 6);
        split6_kernel<<<sg, 256>>>(S, pWHI, pWLO, W_N4);
    }

    embed_kernel<<<L_SEQ, D_MODEL>>>(idx, Wt, bt, Wa, ba, Wm, bm, sos, pAH1, pAL1);
    seg_kernel<<<1, 1024>>>(seqm, pSeg);

    const __nv_bfloat16* wh[6]; const __nv_bfloat16* wl[6];
    for (int j = 0; j < 6; ++j) { wh[j] = pWHI + j * W_ELEMS; wl[j] = pWLO + j * W_ELEMS; }

    dim3 grid1(8, 24, 1), grid3(8, 24, 3);

    for (int layer = 0; layer < 2; ++layer) {
        // QKV: pair1 -> f32 Q,K,V
        {
            GemmOut3 P;
            P.m[0] = {wh[0], wl[0], bq, pQ, nullptr, nullptr};
            P.m[1] = {wh[1], wl[1], bk, pK, nullptr, nullptr};
            P.m[2] = {wh[2], wl[2], bv, pV, nullptr, nullptr};
            gemm_wmma<<<grid3, 128, GT_SMEM>>>(pAH1, pAL1, P, 0);
        }
        // attention -> pair2 hi/lo
        attn_kernel<<<L_SEQ, 128>>>(pQ, pK, pV, pSeg, pAH2, pAL2);
        // Wo: pair2 -> f32 A
        {
            GemmOut3 P; P.m[0] = {wh[3], wl[3], bo, pA, nullptr, nullptr};
            P.m[1] = P.m[0]; P.m[2] = P.m[0];
            gemm_wmma<<<grid1, 128, GT_SMEM>>>(pAH2, pAL2, P, 0);
        }
        // ln1: A -> f32 XA + pair1 hi/lo
        ln_kernel<<<L_SEQ, 256>>>(pA, nullptr, g1, be1, pXA, pAH1, pAL1);
        // FF1 (leaky): pair1 -> pair2 hi/lo (no f32)
        {
            GemmOut3 P; P.m[0] = {wh[4], wl[4], b1, nullptr, pAH2, pAL2};
            P.m[1] = P.m[0]; P.m[2] = P.m[0];
            gemm_wmma<<<grid1, 128, GT_SMEM>>>(pAH1, pAL1, P, 1);
        }
        // FF2: pair2 -> f32 Y
        {
            GemmOut3 P; P.m[0] = {wh[5], wl[5], b2, pY, nullptr, nullptr};
            P.m[1] = P.m[0]; P.m[2] = P.m[0];
            gemm_wmma<<<grid1, 128, GT_SMEM>>>(pAH2, pAL2, P, 0);
        }
        // ln2: Y + XA -> f32 (x2 or out) + pair1 hi/lo for next layer QKV
        ln_kernel<<<L_SEQ, 256>>>(pY, pXA, g2, be2,
                                  (layer == 0) ? pX2 : out, pAH1, pAL1);
    }
}

// round 13
// speedup vs baseline: 1.2600x; 1.1743x over previous
#include <cuda_runtime.h>
#include <cuda_fp16.h>
#include <mma.h>
#include <cstdint>

using namespace nvcuda;

#define L_SEQ 3072
#define D_MODEL 512
#define N_TOKENS 3071

// ======================= scratch (allocation-free) =============================
__device__ float g_Q [L_SEQ * D_MODEL];
__device__ float g_K [L_SEQ * D_MODEL];
__device__ float g_V [L_SEQ * D_MODEL];
__device__ float g_A [L_SEQ * D_MODEL];
__device__ float g_XA[L_SEQ * D_MODEL];
__device__ float g_Y [L_SEQ * D_MODEL];
__device__ float g_X2[L_SEQ * D_MODEL];
__device__ int   g_SEG[L_SEQ];

// activation hi/lo fp16 pairs (two ping-pong pairs), 16B-aligned
__device__ uint4 g_AH1[L_SEQ * D_MODEL * 2 / 16];
__device__ uint4 g_AL1[L_SEQ * D_MODEL * 2 / 16];
__device__ uint4 g_AH2[L_SEQ * D_MODEL * 2 / 16];
__device__ uint4 g_AL2[L_SEQ * D_MODEL * 2 / 16];
__device__ uint4 g_WF [6 * D_MODEL * D_MODEL * 2 / 16];   // weights single fp16

// ======================= fused weight -> fp16 (all 6 in one launch) ===========
struct SplitSrc { const float* s[6]; };

__global__ void __launch_bounds__(256)
split6_kernel(SplitSrc S, __half* __restrict__ wBase, int n4)
{
    const int j = blockIdx.y;
    const float* src = S.s[j];
    __half* w = wBase + j * (D_MODEL * D_MODEL);
    int i = blockIdx.x * blockDim.x + threadIdx.x;
    if (i >= n4) return;
    float4 v = ((const float4*)src)[i];
    __half2 a = __halves2half2(__float2half(v.x), __float2half(v.y));
    __half2 b = __halves2half2(__float2half(v.z), __float2half(v.w));
    uint2 u;
    u.x = *(uint32_t*)&a; u.y = *(uint32_t*)&b;
    ((uint2*)w)[i] = u;
}

// ======================= WMMA fp16x2 pipelined GEMM ===========================
// C[M,N] = A[M,512] @ B[N,512]^T + bias ; A pre-split hi/lo fp16 (hi+lo ~ 22-bit
// mantissa), B single fp16. Two MMA passes: Ahi*B + Alo*B. fp32 accumulate.
// CTA tile 128x64, K chunks of 64, cp.async double buffer.
// 128 threads = 4 warps; warp tile 32x64 (2x4 fragments).
struct GemmOut { const __half* b; const float* bias; float* cF;
                 __half* cHi; __half* cLo; };
struct GemmOut3 { GemmOut m[3]; };

#define CH    64
#define NCHUNK (512 / CH)            // 8
#define LDSK  72
#define SM_AH 0
#define SM_AL (128 * LDSK)
#define SM_B  (2 * 128 * LDSK)
#define BUF_ELEMS (2 * 128 * LDSK + 64 * LDSK)       // 23040 half
#define GT_SMEM (2 * BUF_ELEMS * 2)                   // 92160 B

__device__ __forceinline__ uint32_t smem_u32(const void* p) {
    uint32_t a;
    asm("{ .reg .u64 t; cvta.to.shared.u64 t, %1; cvt.u32.u64 %0, t; }" : "=r"(a) : "l"(p));
    return a;
}
__device__ __forceinline__ void cp16(uint32_t sdst, const void* gsrc) {
    asm volatile("cp.async.cg.shared.global [%0], [%1], 16;" :: "r"(sdst), "l"(gsrc));
}

__global__ void __launch_bounds__(128, 2)
gemm_wmma(const __half* __restrict__ Ahi, const __half* __restrict__ Alo,
          GemmOut3 P, int act)
{
    extern __shared__ __align__(128) __half smem[];
    const GemmOut g = P.m[blockIdx.z];
    const uint32_t sb = smem_u32(smem);
    const int tid  = threadIdx.x;
    const int wid  = tid >> 5;     // 0..3 = M-warp
    const int lane = tid & 31;
    const int rowM0 = blockIdx.y * 128;
    const int colN0 = blockIdx.x * 64;

    const __half* gAh = Ahi + rowM0 * 512;
    const __half* gAl = Alo + rowM0 * 512;
    const __half* gB  = g.b + colN0 * 512;

#define ISSUE(cc, buf) do {                                                          \
        const int koff = (cc) * CH;                                                  \
        const uint32_t bb = sb + (uint32_t)(buf) * (BUF_ELEMS * 2);                  \
        _Pragma("unroll")                                                            \
        for (int i = 0; i < 8; ++i) {                                                \
            int id = tid + i * 128;            /* 0..1023 */                         \
            int r = id >> 3, c8 = (id & 7) * 8;                                      \
            cp16(bb + (SM_AH + r * LDSK + c8) * 2, gAh + r * 512 + koff + c8);       \
            cp16(bb + (SM_AL + r * LDSK + c8) * 2, gAl + r * 512 + koff + c8);       \
        }                                                                            \
        _Pragma("unroll")                                                            \
        for (int i = 0; i < 4; ++i) {                                                \
            int id = tid + i * 128;            /* 0..511 */                          \
            int r = id >> 3, c8 = (id & 7) * 8;                                      \
            cp16(bb + (SM_B + r * LDSK + c8) * 2, gB + r * 512 + koff + c8);         \
        }                                                                            \
        asm volatile("cp.async.commit_group;");                                      \
    } while (0)

    wmma::fragment<wmma::accumulator, 16, 16, 16, float> acc[2][4];
#pragma unroll
    for (int mt = 0; mt < 2; ++mt)
#pragma unroll
        for (int nt = 0; nt < 4; ++nt)
            wmma::fill_fragment(acc[mt][nt], 0.0f);

    ISSUE(0, 0);

    for (int c = 0; c < NCHUNK; ++c) {
        if (c < NCHUNK - 1) {
            ISSUE(c + 1, (c + 1) & 1);
            asm volatile("cp.async.wait_group 1;");
        } else {
            asm volatile("cp.async.wait_group 0;");
        }
        __syncthreads();

        const __half* sAh = smem + (c & 1) * BUF_ELEMS + SM_AH;
        const __half* sAl = smem + (c & 1) * BUF_ELEMS + SM_AL;
        const __half* sB  = smem + (c & 1) * BUF_ELEMS + SM_B;

#pragma unroll
        for (int k16 = 0; k16 < CH / 16; ++k16) {
            wmma::fragment<wmma::matrix_a, 16, 16, 16, __half, wmma::row_major> ah[2], al[2];
            wmma::fragment<wmma::matrix_b, 16, 16, 16, __half, wmma::col_major> bf[4];
#pragma unroll
            for (int mt = 0; mt < 2; ++mt) {
                const int arow = wid * 32 + mt * 16;
                wmma::load_matrix_sync(ah[mt], sAh + arow * LDSK + k16 * 16, LDSK);
                wmma::load_matrix_sync(al[mt], sAl + arow * LDSK + k16 * 16, LDSK);
            }
#pragma unroll
            for (int nt = 0; nt < 4; ++nt)
                wmma::load_matrix_sync(bf[nt], sB + (nt * 16) * LDSK + k16 * 16, LDSK);
#pragma unroll
            for (int mt = 0; mt < 2; ++mt)
#pragma unroll
                for (int nt = 0; nt < 4; ++nt) {
                    wmma::mma_sync(acc[mt][nt], ah[mt], bf[nt], acc[mt][nt]);
                    wmma::mma_sync(acc[mt][nt], al[mt], bf[nt], acc[mt][nt]);
                }
        }
        __syncthreads();
    }
#undef ISSUE

    // ---------------- epilogue: warp stages 32x64 f32 in smem -----------------
    float* warpArea = (float*)smem + wid * (32 * 64);
#pragma unroll
    for (int mt = 0; mt < 2; ++mt)
#pragma unroll
        for (int nt = 0; nt < 4; ++nt)
            wmma::store_matrix_sync(warpArea + mt * 16 * 64 + nt * 16,
                                    acc[mt][nt], 64, wmma::mem_row_major);
    __syncwarp();

    const int grow = rowM0 + wid * 32 + lane;
    const float* bi = g.bias + colN0;
    const float* srow = warpArea + lane * 64;
#pragma unroll
    for (int j = 0; j < 16; ++j) {
        float4 v  = *(const float4*)(srow + j * 4);
        float4 bz = *(const float4*)(bi + j * 4);
        float4 o;
        o.x = v.x + bz.x; o.y = v.y + bz.y; o.z = v.z + bz.z; o.w = v.w + bz.w;
        if (act) {
            o.x = o.x > 0.f ? o.x : 0.01f * o.x;
            o.y = o.y > 0.f ? o.y : 0.01f * o.y;
            o.z = o.z > 0.f ? o.z : 0.01f * o.z;
            o.w = o.w > 0.f ? o.w : 0.01f * o.w;
        }
        if (g.cF) *(float4*)(g.cF + grow * 512 + colN0 + j * 4) = o;
        if (g.cHi) {
            __half h0 = __float2half(o.x), h1 = __float2half(o.y);
            __half h2 = __float2half(o.z), h3 = __float2half(o.w);
            __half l0 = __float2half(o.x - __half2float(h0));
            __half l1 = __float2half(o.y - __half2float(h1));
            __half l2 = __float2half(o.z - __half2float(h2));
            __half l3 = __float2half(o.w - __half2float(h3));
            __half2 hA = __halves2half2(h0, h1), hB = __halves2half2(h2, h3);
            __half2 lA = __halves2half2(l0, l1), lB = __halves2half2(l2, l3);
            uint2 uh, ul;
            uh.x = *(uint32_t*)&hA; uh.y = *(uint32_t*)&hB;
            ul.x = *(uint32_t*)&lA; ul.y = *(uint32_t*)&lB;
            *(uint2*)(g.cHi + grow * 512 + colN0 + j * 4) = uh;
            *(uint2*)(g.cLo + grow * 512 + colN0 + j * 4) = ul;
        }
    }
}

// ======================= embedding (emits fp16 hi/lo directly) ================
__global__ void embed_kernel(const int* __restrict__ idx,
                             const float* __restrict__ Wt, const float* __restrict__ bt,
                             const float* __restrict__ Wa, const float* __restrict__ ba,
                             const float* __restrict__ Wm, const float* __restrict__ bm,
                             const float* __restrict__ sos,
                             __half* __restrict__ XH, __half* __restrict__ XL)
{
    int n = blockIdx.x;
    int d = threadIdx.x;             // 512 threads
    float r;
    if (n == 0) {
        r = sos[d];
    } else {
        int id = idx[n - 1];
        int t  = id / 219;           // N_ARGS*N_MAPS = 73*3
        int a  = (id / 3) % 73;
        int m  = id % 3;
        r = bt[d] + ba[d] + bm[d];
        r += Wt[d * 15 + t];
        r += Wa[d * 73 + a];
        r += Wm[d * 3  + m];
    }
    __half h = __float2half(r);
    __half l = __float2half(r - __half2float(h));
    XH[n * D_MODEL + d] = h;
    XL[n * D_MODEL + d] = l;
}

// ======================= segment-start parallel max-scan ======================
__global__ void __launch_bounds__(1024)
seg_kernel(const int* __restrict__ seq_masks, int* __restrict__ seg)
{
    __shared__ int bnd[L_SEQ];
    __shared__ int tmax[1024];
    const int t = threadIdx.x;
    int run = 0;
#pragma unroll
    for (int e = 0; e < 3; ++e) {
        int i = t * 3 + e;
        int v;
        if (i == 0)      v = 0;
        else if (i == 1) v = 1;
        else             v = (seq_masks[i - 1] == 0) ? i : 0;
        run = max(run, v);
        bnd[i] = run;
    }
    tmax[t] = run;
    __syncthreads();
    for (int o = 1; o < 1024; o <<= 1) {
        int u = (t >= o) ? tmax[t - o] : 0;
        __syncthreads();
        tmax[t] = max(tmax[t], u);
        __syncthreads();
    }
    int excl = (t == 0) ? 0 : tmax[t - 1];
#pragma unroll
    for (int e = 0; e < 3; ++e) {
        int i = t * 3 + e;
        seg[i] = max(bnd[i], excl);
    }
}

// ======================= segment-sparse attention (float4, emits fp16 hi/lo) ==
// 128 threads: warp w holds heads 2w, 2w+1; 16 lanes x float4 per head.
__global__ void __launch_bounds__(128)
attn_kernel(const float* __restrict__ Q, const float* __restrict__ K,
            const float* __restrict__ V, const int* __restrict__ seg,
            __half* __restrict__ OH, __half* __restrict__ OL)
{
    const int i    = blockIdx.x;
    const int w    = threadIdx.x >> 5;
    const int lane = threadIdx.x & 31;
    const int h    = (w << 1) + (lane >> 4);   // head 0..7
    const int sl   = lane & 15;
    const int base = (h << 6) + (sl << 2);     // h*64 + sl*4

    float4 q = *(const float4*)(Q + i * D_MODEL + base);
    q.x *= 0.125f; q.y *= 0.125f; q.z *= 0.125f; q.w *= 0.125f;

    float m = -1e30f, l = 0.f;
    float a0 = 0.f, a1 = 0.f, a2 = 0.f, a3 = 0.f;
    const int s = seg[i];

    int j = 0;
    bool first = true;
    for (;;) {
        float4 kv = *(const float4*)(K + j * D_MODEL + base);
        float p = q.x * kv.x + q.y * kv.y + q.z * kv.z + q.w * kv.w;
#pragma unroll
        for (int o = 8; o; o >>= 1) p += __shfl_xor_sync(0xffffffffu, p, o);
        float mnew = fmaxf(m, p);
        float corr = __expf(m - mnew);
        float pe   = __expf(p - mnew);
        float4 vv = *(const float4*)(V + j * D_MODEL + base);
        l  = l  * corr + pe;
        a0 = a0 * corr + pe * vv.x;
        a1 = a1 * corr + pe * vv.y;
        a2 = a2 * corr + pe * vv.z;
        a3 = a3 * corr + pe * vv.w;
        m = mnew;
        if (first) { first = false; j = s; } else { j++; }
        if (j >= i) break;
    }

    float inv = 1.f / l;
    float o0 = a0 * inv, o1 = a1 * inv, o2 = a2 * inv, o3 = a3 * inv;
    __half h0 = __float2half(o0), h1 = __float2half(o1);
    __half h2 = __float2half(o2), h3 = __float2half(o3);
    __half l0 = __float2half(o0 - __half2float(h0));
    __half l1 = __float2half(o1 - __half2float(h1));
    __half l2 = __float2half(o2 - __half2float(h2));
    __half l3 = __float2half(o3 - __half2float(h3));
    __half2 hA = __halves2half2(h0, h1), hB = __halves2half2(h2, h3);
    __half2 lA = __halves2half2(l0, l1), lB = __halves2half2(l2, l3);
    uint2 uh, ul;
    uh.x = *(uint32_t*)&hA; uh.y = *(uint32_t*)&hB;
    ul.x = *(uint32_t*)&lA; ul.y = *(uint32_t*)&lB;
    *(uint2*)(OH + i * D_MODEL + base) = uh;
    *(uint2*)(OL + i * D_MODEL + base) = ul;
}

// ======================= LayerNorm (residual opt; f32 + fp16 hi/lo outs) ======
__global__ void __launch_bounds__(256)
ln_kernel(const float* __restrict__ X, const float* __restrict__ R,
          const float* __restrict__ g, const float* __restrict__ b,
          float* __restrict__ OutF,
          __half* __restrict__ OutH, __half* __restrict__ OutL)
{
    const int row = blockIdx.x;
    const int t   = threadIdx.x;
    float2 v = *(const float2*)(X + row * D_MODEL + (t << 1));
    if (R) {
        float2 r = *(const float2*)(R + row * D_MODEL + (t << 1));
        v.x += r.x; v.y += r.y;
    }
    float s  = v.x + v.y;
    float sq = v.x * v.x + v.y * v.y;
#pragma unroll
    for (int o = 16; o; o >>= 1) {
        s  += __shfl_xor_sync(0xffffffffu, s,  o);
        sq += __shfl_xor_sync(0xffffffffu, sq, o);
    }
    __shared__ float ss[8], sqs[8];
    const int warp = t >> 5, lane = t & 31;
    if (lane == 0) { ss[warp] = s; sqs[warp] = sq; }
    __syncthreads();
    if (warp == 0) {
        float a = (lane < 8) ? ss[lane]  : 0.f;
        float c = (lane < 8) ? sqs[lane] : 0.f;
#pragma unroll
        for (int o = 4; o; o >>= 1) {
            a += __shfl_xor_sync(0xffffffffu, a, o);
            c += __shfl_xor_sync(0xffffffffu, c, o);
        }
        if (lane == 0) { ss[0] = a; sqs[0] = c; }
    }
    __syncthreads();
    const float mu  = ss[0]  * (1.f / 512.f);
    const float var = sqs[0] * (1.f / 512.f) - mu * mu;
    const float inv = rsqrtf(var + 1e-5f);
    float2 gg = *(const float2*)(g + (t << 1));
    float2 bb = *(const float2*)(b + (t << 1));
    float ox = (v.x - mu) * inv * gg.x + bb.x;
    float oy = (v.y - mu) * inv * gg.y + bb.y;
    if (OutF) {
        float2 o; o.x = ox; o.y = oy;
        *(float2*)(OutF + row * D_MODEL + (t << 1)) = o;
    }
    if (OutH) {
        __half h0 = __float2half(ox), h1 = __float2half(oy);
        __half l0 = __float2half(ox - __half2float(h0));
        __half l1 = __float2half(oy - __half2float(h1));
        __half2 hv = __halves2half2(h0, h1), lv = __halves2half2(l0, l1);
        *(__half2*)(OutH + row * D_MODEL + (t << 1)) = hv;
        *(__half2*)(OutL + row * D_MODEL + (t << 1)) = lv;
    }
}

// ======================= host orchestration ===================================
#define W_ELEMS (D_MODEL * D_MODEL)
#define W_N4    (W_ELEMS / 4)

extern "C" void kernel_launch(void* const* d_in, const int* in_sizes, int n_in,
                              void* d_out, int out_size)
{
    const int*   idx  = (const int*)  d_in[0];
    const int*   seqm = (const int*)  d_in[1];
    const float* Wt   = (const float*)d_in[2];
    const float* bt   = (const float*)d_in[3];
    const float* Wa   = (const float*)d_in[4];
    const float* ba   = (const float*)d_in[5];
    const float* Wm   = (const float*)d_in[6];
    const float* bm   = (const float*)d_in[7];
    const float* sos  = (const float*)d_in[8];
    const float* Wq   = (const float*)d_in[9];
    const float* bq   = (const float*)d_in[10];
    const float* Wk   = (const float*)d_in[11];
    const float* bk   = (const float*)d_in[12];
    const float* Wv   = (const float*)d_in[13];
    const float* bv   = (const float*)d_in[14];
    const float* Wo   = (const float*)d_in[15];
    const float* bo   = (const float*)d_in[16];
    const float* W1   = (const float*)d_in[17];
    const float* b1   = (const float*)d_in[18];
    const float* W2   = (const float*)d_in[19];
    const float* b2   = (const float*)d_in[20];
    const float* g1   = (const float*)d_in[21];
    const float* be1  = (const float*)d_in[22];
    const float* g2   = (const float*)d_in[23];
    const float* be2  = (const float*)d_in[24];
    float* out = (float*)d_out;

    float *pQ, *pK, *pV, *pA, *pXA, *pY, *pX2;
    int* pSeg;
    __half *pAH1, *pAL1, *pAH2, *pAL2, *pWF;
    cudaGetSymbolAddress((void**)&pQ,  g_Q);
    cudaGetSymbolAddress((void**)&pK,  g_K);
    cudaGetSymbolAddress((void**)&pV,  g_V);
    cudaGetSymbolAddress((void**)&pA,  g_A);
    cudaGetSymbolAddress((void**)&pXA, g_XA);
    cudaGetSymbolAddress((void**)&pY,  g_Y);
    cudaGetSymbolAddress((void**)&pX2, g_X2);
    cudaGetSymbolAddress((void**)&pSeg, g_SEG);
    cudaGetSymbolAddress((void**)&pAH1, g_AH1);
    cudaGetSymbolAddress((void**)&pAL1, g_AL1);
    cudaGetSymbolAddress((void**)&pAH2, g_AH2);
    cudaGetSymbolAddress((void**)&pAL2, g_AL2);
    cudaGetSymbolAddress((void**)&pWF,  g_WF);

    cudaFuncSetAttribute(gemm_wmma, cudaFuncAttributeMaxDynamicSharedMemorySize, GT_SMEM);

    // weight -> fp16: order q,k,v,o,w1,w2 — single fused launch
    {
        SplitSrc S; S.s[0] = Wq; S.s[1] = Wk; S.s[2] = Wv;
        S.s[3] = Wo; S.s[4] = W1; S.s[5] = W2;
        dim3 sg(W_N4 / 256, 6);
        split6_kernel<<<sg, 256>>>(S, pWF, W_N4);
    }

    embed_kernel<<<L_SEQ, D_MODEL>>>(idx, Wt, bt, Wa, ba, Wm, bm, sos, pAH1, pAL1);
    seg_kernel<<<1, 1024>>>(seqm, pSeg);

    const __half* wf[6];
    for (int j = 0; j < 6; ++j) wf[j] = pWF + j * W_ELEMS;

    dim3 grid1(8, 24, 1), grid3(8, 24, 3);

    for (int layer = 0; layer < 2; ++layer) {
        // QKV: pair1 -> f32 Q,K,V
        {
            GemmOut3 P;
            P.m[0] = {wf[0], bq, pQ, nullptr, nullptr};
            P.m[1] = {wf[1], bk, pK, nullptr, nullptr};
            P.m[2] = {wf[2], bv, pV, nullptr, nullptr};
            gemm_wmma<<<grid3, 128, GT_SMEM>>>(pAH1, pAL1, P, 0);
        }
        // attention -> pair2 hi/lo
        attn_kernel<<<L_SEQ, 128>>>(pQ, pK, pV, pSeg, pAH2, pAL2);
        // Wo: pair2 -> f32 A
        {
            GemmOut3 P; P.m[0] = {wf[3], bo, pA, nullptr, nullptr};
            P.m[1] = P.m[0]; P.m[2] = P.m[0];
            gemm_wmma<<<grid1, 128, GT_SMEM>>>(pAH2, pAL2, P, 0);
        }
        // ln1: A -> f32 XA + pair1 hi/lo
        ln_kernel<<<L_SEQ, 256>>>(pA, nullptr, g1, be1, pXA, pAH1, pAL1);
        // FF1 (leaky): pair1 -> pair2 hi/lo (no f32)
        {
            GemmOut3 P; P.m[0] = {wf[4], b1, nullptr, pAH2, pAL2};
            P.m[1] = P.m[0]; P.m[2] = P.m[0];
            gemm_wmma<<<grid1, 128, GT_SMEM>>>(pAH1, pAL1, P, 1);
        }
        // FF2: pair2 -> f32 Y
        {
            GemmOut3 P; P.m[0] = {wf[5], b2, pY, nullptr, nullptr};
            P.m[1] = P.m[0]; P.m[2] = P.m[0];
            gemm_wmma<<<grid1, 128, GT_SMEM>>>(pAH2, pAL2, P, 0);
        }
        // ln2: Y + XA -> f32 (x2 or out) + pair1 hi/lo for next layer QKV
        ln_kernel<<<L_SEQ, 256>>>(pY, pXA, g2, be2,
                                  (layer == 0) ? pX2 : out, pAH1, pAL1);
    }
}